// round 9
// baseline (speedup 1.0000x reference)
#include <cuda_runtime.h>
#include <math.h>
#include <stdint.h>

#define NN   50000
#define FIN  256
#define FH   64
#define FOUT 32
#define EMAX 800000
#define NEG_SLOPE 0.01f

// ---------------- scratch (static device globals; no allocation) ----------------
__device__ __align__(16) float g_h[3][NN * FH];     // x @ W per branch (tf32 mma)
__device__ __align__(16) float g_e[3][NN * FH];     // relu'd layer-1 embeddings
__device__ float g_dinv[3][NN];                     // deg (then rsqrt(deg))
__device__ __align__(16) float g_comb[NN * FH];     // attention-combined embedding
__device__ __align__(16) float g_g[3][NN * FOUT];   // combined @ W_kk
// CSR (grouped by dst) per branch
__device__ int   g_cnt [3][NN];
__device__ int   g_fill[3][NN];
__device__ int   g_offs[3][NN + 1];
__device__ int   g_csrc [3][EMAX];
__device__ float g_cnorm[3][EMAX];

// round fp32 -> tf32, result as fp32 bits
__device__ __forceinline__ float tf32r(float v) {
    uint32_t u;
    asm("cvt.rna.tf32.f32 %0, %1;" : "=r"(u) : "f"(v));
    return __uint_as_float(u);
}

__device__ __forceinline__ void mma_tf32(float* c, const uint32_t* a, uint32_t b0, uint32_t b1) {
    asm volatile("mma.sync.aligned.m16n8k8.row.col.f32.tf32.tf32.f32 "
                 "{%0,%1,%2,%3}, {%4,%5,%6,%7}, {%8,%9}, {%0,%1,%2,%3};"
                 : "+f"(c[0]), "+f"(c[1]), "+f"(c[2]), "+f"(c[3])
                 : "r"(a[0]), "r"(a[1]), "r"(a[2]), "r"(a[3]), "r"(b0), "r"(b1));
}

// ---------------- init: zero counters, deg = 1 (self-loop) ----------------
__global__ void k_init() {
    int stride = gridDim.x * blockDim.x;
    int i0 = blockIdx.x * blockDim.x + threadIdx.x;
    int* cf = &g_cnt[0][0];
    for (int i = i0; i < 3 * NN; i += stride) cf[i] = 0;
    float* df = &g_dinv[0][0];
    for (int i = i0; i < 3 * NN; i += stride) df[i] = 1.0f;
}

// ---------------- degree sum + in-degree count (blockIdx.y = branch) ----------------
__global__ void k_degcnt(const int* __restrict__ s0, const int* __restrict__ s1, const int* __restrict__ s2,
                         const float* __restrict__ w0, const float* __restrict__ w1, const float* __restrict__ w2,
                         int E) {
    int br = blockIdx.y;
    const int* ei = br == 0 ? s0 : br == 1 ? s1 : s2;   // dst at +E
    const float* w = br == 0 ? w0 : br == 1 ? w1 : w2;
    int e = blockIdx.x * blockDim.x + threadIdx.x;
    if (e < E) {
        int d = ei[E + e];
        atomicAdd(&g_dinv[br][d], w[e]);
        atomicAdd(&g_cnt[br][d], 1);
    }
}

__global__ void k_rsqrt() {
    int i = blockIdx.x * blockDim.x + threadIdx.x;
    float* df = &g_dinv[0][0];
    if (i < 3 * NN) df[i] = rsqrtf(df[i]);
}

// ---------------- exclusive scan of cnt -> offs, fill (one block per branch) ----------------
__global__ void k_scan() {
    __shared__ int ssum[1024];
    int br = blockIdx.x;
    int t = threadIdx.x;
    const int PER = (NN + 1023) / 1024;   // 49
    int base = t * PER;
    int lim = base + PER; if (lim > NN) lim = NN;
    int s = 0;
    for (int i = base; i < lim; i++) s += g_cnt[br][i];
    ssum[t] = s;
    __syncthreads();
    // inclusive Hillis-Steele scan over 1024 partials
    for (int off = 1; off < 1024; off <<= 1) {
        int v = (t >= off) ? ssum[t - off] : 0;
        __syncthreads();
        ssum[t] += v;
        __syncthreads();
    }
    int run = (t == 0) ? 0 : ssum[t - 1];
    for (int i = base; i < lim; i++) {
        g_offs[br][i] = run;
        g_fill[br][i] = run;
        run += g_cnt[br][i];
    }
    if (t == 1023) g_offs[br][NN] = run;
}

// ---------------- bucket edges into CSR; norm computed here (fuses old k_norm) ----------------
__global__ void k_bucket(const int* __restrict__ s0, const int* __restrict__ s1, const int* __restrict__ s2,
                         const float* __restrict__ w0, const float* __restrict__ w1, const float* __restrict__ w2,
                         int E) {
    int br = blockIdx.y;
    const int* ei = br == 0 ? s0 : br == 1 ? s1 : s2;
    const float* w = br == 0 ? w0 : br == 1 ? w1 : w2;
    int e = blockIdx.x * blockDim.x + threadIdx.x;
    if (e >= E) return;
    int s = ei[e];
    int d = ei[E + e];
    float nv = g_dinv[br][s] * w[e] * g_dinv[br][d];
    int pos = atomicAdd(&g_fill[br][d], 1);
    g_csrc[br][pos] = s;
    g_cnorm[br][pos] = nv;
}

// ---------------- GEMM1 (tf32 mma, error-compensated): [NN,256]@[256,64] -> g_h ----------------
__global__ void k_gemm1(const float* __restrict__ X0, const float* __restrict__ X1, const float* __restrict__ X2,
                        const float* __restrict__ W0, const float* __restrict__ W1, const float* __restrict__ W2) {
    int br = blockIdx.y;
    const float* X = br == 0 ? X0 : br == 1 ? X1 : X2;
    const float* W = br == 0 ? W0 : br == 1 ? W1 : W2;

    __shared__ float xs_hi[128][20], xs_lo[128][20];
    __shared__ float ws_hi[16][72], ws_lo[16][72];

    int tid = threadIdx.x;
    int warp = tid >> 5, lane = tid & 31;
    int group = lane >> 2, tig = lane & 3;
    int m0 = blockIdx.x * 128;

    float c[8][4] = {};

    for (int k0 = 0; k0 < FIN; k0 += 16) {
        #pragma unroll
        for (int i = 0; i < 2; i++) {
            int idx = tid + i * 256;
            int r = idx >> 2;
            int cc = (idx & 3) * 4;
            float4 v = make_float4(0.f, 0.f, 0.f, 0.f);
            if (m0 + r < NN) v = *(const float4*)(X + (size_t)(m0 + r) * FIN + k0 + cc);
            float h0 = tf32r(v.x), h1 = tf32r(v.y), h2 = tf32r(v.z), h3 = tf32r(v.w);
            xs_hi[r][cc + 0] = h0; xs_hi[r][cc + 1] = h1; xs_hi[r][cc + 2] = h2; xs_hi[r][cc + 3] = h3;
            xs_lo[r][cc + 0] = tf32r(v.x - h0); xs_lo[r][cc + 1] = tf32r(v.y - h1);
            xs_lo[r][cc + 2] = tf32r(v.z - h2); xs_lo[r][cc + 3] = tf32r(v.w - h3);
        }
        {
            int kr = tid >> 4;
            int cc = (tid & 15) * 4;
            float4 v = *(const float4*)(W + (size_t)(k0 + kr) * FH + cc);
            float h0 = tf32r(v.x), h1 = tf32r(v.y), h2 = tf32r(v.z), h3 = tf32r(v.w);
            ws_hi[kr][cc + 0] = h0; ws_hi[kr][cc + 1] = h1; ws_hi[kr][cc + 2] = h2; ws_hi[kr][cc + 3] = h3;
            ws_lo[kr][cc + 0] = tf32r(v.x - h0); ws_lo[kr][cc + 1] = tf32r(v.y - h1);
            ws_lo[kr][cc + 2] = tf32r(v.z - h2); ws_lo[kr][cc + 3] = tf32r(v.w - h3);
        }
        __syncthreads();

        #pragma unroll
        for (int kk = 0; kk < 16; kk += 8) {
            int ar = warp * 16 + group;
            uint32_t a_hi[4], a_lo[4];
            a_hi[0] = __float_as_uint(xs_hi[ar][kk + tig]);
            a_hi[1] = __float_as_uint(xs_hi[ar + 8][kk + tig]);
            a_hi[2] = __float_as_uint(xs_hi[ar][kk + tig + 4]);
            a_hi[3] = __float_as_uint(xs_hi[ar + 8][kk + tig + 4]);
            a_lo[0] = __float_as_uint(xs_lo[ar][kk + tig]);
            a_lo[1] = __float_as_uint(xs_lo[ar + 8][kk + tig]);
            a_lo[2] = __float_as_uint(xs_lo[ar][kk + tig + 4]);
            a_lo[3] = __float_as_uint(xs_lo[ar + 8][kk + tig + 4]);
            #pragma unroll
            for (int nt = 0; nt < 8; nt++) {
                int n = nt * 8 + group;
                uint32_t bh0 = __float_as_uint(ws_hi[kk + tig][n]);
                uint32_t bh1 = __float_as_uint(ws_hi[kk + tig + 4][n]);
                uint32_t bl0 = __float_as_uint(ws_lo[kk + tig][n]);
                uint32_t bl1 = __float_as_uint(ws_lo[kk + tig + 4][n]);
                mma_tf32(c[nt], a_hi, bh0, bh1);
                mma_tf32(c[nt], a_lo, bh0, bh1);
                mma_tf32(c[nt], a_hi, bl0, bl1);
            }
        }
        __syncthreads();
    }

    float* H = &g_h[br][0];
    int r0 = m0 + warp * 16 + group;
    #pragma unroll
    for (int nt = 0; nt < 8; nt++) {
        int col = nt * 8 + tig * 2;
        if (r0 < NN)     *(float2*)(H + (size_t)r0 * FH + col)       = make_float2(c[nt][0], c[nt][1]);
        if (r0 + 8 < NN) *(float2*)(H + (size_t)(r0 + 8) * FH + col) = make_float2(c[nt][2], c[nt][3]);
    }
}

// ---------------- layer-1 aggregation: warp per node, gather-only, fused epilogue ----------------
__global__ void k_agg1(const float* __restrict__ b1, const float* __restrict__ b2,
                       const float* __restrict__ b3) {
    int br = blockIdx.y;
    int node = (blockIdx.x * blockDim.x + threadIdx.x) >> 5;
    int lane = threadIdx.x & 31;
    if (node >= NN) return;
    const float2* H2 = (const float2*)&g_h[br][0];
    const int*    cs = &g_csrc[br][0];
    const float*  cn = &g_cnorm[br][0];
    int j   = g_offs[br][node];
    int end = g_offs[br][node + 1];
    float2 acc0 = make_float2(0.f, 0.f), acc1 = make_float2(0.f, 0.f);
    for (; j + 2 <= end; j += 2) {
        int   s0 = cs[j],     s1 = cs[j + 1];
        float n0 = cn[j],     n1 = cn[j + 1];
        float2 h0 = H2[(size_t)s0 * 32 + lane];
        float2 h1 = H2[(size_t)s1 * 32 + lane];
        acc0.x += n0 * h0.x; acc0.y += n0 * h0.y;
        acc1.x += n1 * h1.x; acc1.y += n1 * h1.y;
    }
    if (j < end) {
        int s0 = cs[j]; float n0 = cn[j];
        float2 h0 = H2[(size_t)s0 * 32 + lane];
        acc0.x += n0 * h0.x; acc0.y += n0 * h0.y;
    }
    float di = g_dinv[br][node]; di *= di;
    float2 hn = H2[(size_t)node * 32 + lane];
    const float* b = br == 0 ? b1 : br == 1 ? b2 : b3;
    float2 bb = ((const float2*)b)[lane];
    float2 ev;
    ev.x = fmaxf(acc0.x + acc1.x + di * hn.x + bb.x, 0.f);
    ev.y = fmaxf(acc0.y + acc1.y + di * hn.y + bb.y, 0.f);
    ((float2*)&g_e[br][0])[(size_t)node * 32 + lane] = ev;
}

// ---------------- attention: warp per node (e already relu'd) ----------------
__global__ void k_attn(const float* __restrict__ fcw, const float* __restrict__ fcb,
                       float* __restrict__ out_coef) {
    int node = (blockIdx.x * blockDim.x + threadIdx.x) >> 5;
    int lane = threadIdx.x & 31;
    if (node >= NN) return;
    float2 e1 = ((const float2*)&g_e[0][0])[(size_t)node * 32 + lane];
    float2 e2 = ((const float2*)&g_e[1][0])[(size_t)node * 32 + lane];
    float2 e3 = ((const float2*)&g_e[2][0])[(size_t)node * 32 + lane];
    float2 w2 = ((const float2*)fcw)[lane];
    float d1 = e1.x * w2.x + e1.y * w2.y;
    float d2 = e2.x * w2.x + e2.y * w2.y;
    float d3 = e3.x * w2.x + e3.y * w2.y;
    #pragma unroll
    for (int o = 16; o > 0; o >>= 1) {
        d1 += __shfl_xor_sync(0xffffffffu, d1, o);
        d2 += __shfl_xor_sync(0xffffffffu, d2, o);
        d3 += __shfl_xor_sync(0xffffffffu, d3, o);
    }
    float fb = fcb[0];
    float v1 = d1 + fb, v2 = d2 + fb, v3 = d3 + fb;
    v1 = v1 > 0.f ? v1 : v1 * NEG_SLOPE;
    v2 = v2 > 0.f ? v2 : v2 * NEG_SLOPE;
    v3 = v3 > 0.f ? v3 : v3 * NEG_SLOPE;
    float x1 = expf(v1), x2 = expf(v2), x3 = expf(v3);
    float inv = 1.0f / (x1 + x2 + x3);
    float c1 = x1 * inv, c2 = x2 * inv, c3 = x3 * inv;
    float2 cmb;
    cmb.x = c1 * e1.x + c2 * e2.x + c3 * e3.x;
    cmb.y = c1 * e1.y + c2 * e2.y + c3 * e3.y;
    ((float2*)g_comb)[(size_t)node * 32 + lane] = cmb;
    if (lane == 0) {
        out_coef[node]          = c1;
        out_coef[NN + node]     = c2;
        out_coef[2 * NN + node] = c3;
    }
}

// ---------------- GEMM2: [NN,64] @ [64,32] -> g_g[br] ----------------
__global__ void k_gemm2(const float* __restrict__ Wa, const float* __restrict__ Wb,
                        const float* __restrict__ Wc) {
    int br = blockIdx.y;
    const float* W2 = br == 0 ? Wa : br == 1 ? Wb : Wc;
    __shared__ float ws[64][32];
    __shared__ float cs[32][65];
    int tid = threadIdx.x;
    int r0 = blockIdx.x * 32;
    for (int i = tid; i < 512; i += 256)
        ((float4*)ws)[i] = ((const float4*)W2)[i];
    for (int i = tid; i < 512; i += 256) {
        int row = i >> 4, c = (i & 15) * 4;
        int gr = r0 + row;
        float4 v = make_float4(0.f, 0.f, 0.f, 0.f);
        if (gr < NN) v = ((const float4*)g_comb)[(size_t)gr * 16 + (c >> 2)];
        cs[row][c] = v.x; cs[row][c + 1] = v.y; cs[row][c + 2] = v.z; cs[row][c + 3] = v.w;
    }
    __syncthreads();
    int row = tid >> 3, cg = (tid & 7) * 4;
    float4 acc = make_float4(0.f, 0.f, 0.f, 0.f);
    #pragma unroll
    for (int k = 0; k < 64; k++) {
        float a = cs[row][k];
        float4 b = *(const float4*)&ws[k][cg];
        acc.x += a * b.x; acc.y += a * b.y; acc.z += a * b.z; acc.w += a * b.w;
    }
    int gr = r0 + row;
    if (gr < NN)
        ((float4*)&g_g[br][0])[(size_t)gr * 8 + (cg >> 2)] = acc;
}

// ---------------- layer-2 aggregation: warp per node, all 3 branches, write d_out ----------------
__global__ void k_agg2(const float* __restrict__ b11, const float* __restrict__ b22,
                       const float* __restrict__ b33, float* __restrict__ out) {
    int node = (blockIdx.x * blockDim.x + threadIdx.x) >> 5;
    int lane = threadIdx.x & 31;
    if (node >= NN) return;
    float acc = 0.f;
    #pragma unroll
    for (int br = 0; br < 3; br++) {
        const float* G  = &g_g[br][0];
        const int*   cs = &g_csrc[br][0];
        const float* cn = &g_cnorm[br][0];
        int j   = g_offs[br][node];
        int end = g_offs[br][node + 1];
        float a0 = 0.f, a1 = 0.f;
        for (; j + 2 <= end; j += 2) {
            int   s0 = cs[j],  s1 = cs[j + 1];
            float n0 = cn[j],  n1 = cn[j + 1];
            a0 += n0 * G[(size_t)s0 * FOUT + lane];
            a1 += n1 * G[(size_t)s1 * FOUT + lane];
        }
        if (j < end) a0 += cn[j] * G[(size_t)cs[j] * FOUT + lane];
        float di = g_dinv[br][node]; di *= di;
        acc += a0 + a1 + di * G[(size_t)node * FOUT + lane];
    }
    acc += b11[lane] + b22[lane] + b33[lane];
    out[(size_t)node * FOUT + lane] = acc;
}

// ---------------- launch ----------------
extern "C" void kernel_launch(void* const* d_in, const int* in_sizes, int n_in,
                              void* d_out, int out_size) {
    const float* x[3]  = {(const float*)d_in[0], (const float*)d_in[1], (const float*)d_in[2]};
    const int*   ei[3] = {(const int*)d_in[3], (const int*)d_in[4], (const int*)d_in[5]};
    const float* ew[3] = {(const float*)d_in[6], (const float*)d_in[7], (const float*)d_in[8]};
    const float* W1[3] = {(const float*)d_in[9], (const float*)d_in[10], (const float*)d_in[11]};
    const float* b1[3] = {(const float*)d_in[12], (const float*)d_in[13], (const float*)d_in[14]};
    const float* fcw   = (const float*)d_in[15];
    const float* fcb   = (const float*)d_in[16];
    const float* W2[3] = {(const float*)d_in[17], (const float*)d_in[18], (const float*)d_in[19]};
    const float* b2[3] = {(const float*)d_in[20], (const float*)d_in[21], (const float*)d_in[22]};
    float* out = (float*)d_out;

    int E = in_sizes[3] / 2;

    k_init<<<256, 256>>>();

    {   dim3 g((E + 255) / 256, 3);
        k_degcnt<<<g, 256>>>(ei[0], ei[1], ei[2], ew[0], ew[1], ew[2], E); }

    k_rsqrt<<<(3 * NN + 255) / 256, 256>>>();

    k_scan<<<3, 1024>>>();

    {   dim3 g((E + 255) / 256, 3);
        k_bucket<<<g, 256>>>(ei[0], ei[1], ei[2], ew[0], ew[1], ew[2], E); }

    {   dim3 g((NN + 127) / 128, 3);
        k_gemm1<<<g, 256>>>(x[0], x[1], x[2], W1[0], W1[1], W1[2]); }

    {   dim3 g((NN * 32 + 255) / 256, 3);
        k_agg1<<<g, 256>>>(b1[0], b1[1], b1[2]); }

    k_attn<<<(NN * 32 + 255) / 256, 256>>>(fcw, fcb, out + NN * FOUT);

    {   dim3 g((NN + 31) / 32, 3);
        k_gemm2<<<g, 256>>>(W2[0], W2[1], W2[2]); }

    k_agg2<<<(NN * 32 + 255) / 256, 256>>>(b2[0], b2[1], b2[2], out);
}

// round 11
// speedup vs baseline: 1.1938x; 1.1938x over previous
#include <cuda_runtime.h>
#include <math.h>
#include <stdint.h>

#define NN   50000
#define FIN  256
#define FH   64
#define FOUT 32
#define EMAX 800000
#define NEG_SLOPE 0.01f
#define NCHUNK ((NN + 1023) / 1024)   // 49

// ---------------- scratch (static device globals; no allocation) ----------------
__device__ __align__(16) float g_h[3][NN * FH];     // x @ W per branch (tf32 mma)
__device__ __align__(16) float g_e[3][NN * FH];     // relu'd layer-1 embeddings
__device__ float g_dinv[3][NN];                     // deg (then rsqrt(deg))
__device__ __align__(16) float g_comb[NN * FH];     // attention-combined embedding
__device__ __align__(16) float g_g[3][NN * FOUT];   // combined @ W_kk
// CSR (grouped by dst) per branch
__device__ int   g_cnt [3][NN];
__device__ int   g_fill[3][NN];
__device__ int   g_offs[3][NN + 1];
__device__ int   g_bsum[3][64];
__device__ int   g_csrc [3][EMAX];
__device__ float g_cnorm[3][EMAX];

// round fp32 -> tf32, result as fp32 bits
__device__ __forceinline__ float tf32r(float v) {
    uint32_t u;
    asm("cvt.rna.tf32.f32 %0, %1;" : "=r"(u) : "f"(v));
    return __uint_as_float(u);
}

__device__ __forceinline__ void mma_tf32(float* c, const uint32_t* a, uint32_t b0, uint32_t b1) {
    asm volatile("mma.sync.aligned.m16n8k8.row.col.f32.tf32.tf32.f32 "
                 "{%0,%1,%2,%3}, {%4,%5,%6,%7}, {%8,%9}, {%0,%1,%2,%3};"
                 : "+f"(c[0]), "+f"(c[1]), "+f"(c[2]), "+f"(c[3])
                 : "r"(a[0]), "r"(a[1]), "r"(a[2]), "r"(a[3]), "r"(b0), "r"(b1));
}

// ---------------- init: zero counters, deg = 1 (self-loop) ----------------
__global__ void k_init() {
    int stride = gridDim.x * blockDim.x;
    int i0 = blockIdx.x * blockDim.x + threadIdx.x;
    int* cf = &g_cnt[0][0];
    for (int i = i0; i < 3 * NN; i += stride) cf[i] = 0;
    float* df = &g_dinv[0][0];
    for (int i = i0; i < 3 * NN; i += stride) df[i] = 1.0f;
}

// ---------------- degree sum + in-degree count (blockIdx.y = branch) ----------------
__global__ void k_degcnt(const int* __restrict__ s0, const int* __restrict__ s1, const int* __restrict__ s2,
                         const float* __restrict__ w0, const float* __restrict__ w1, const float* __restrict__ w2,
                         int E) {
    int br = blockIdx.y;
    const int* ei = br == 0 ? s0 : br == 1 ? s1 : s2;   // dst at +E
    const float* w = br == 0 ? w0 : br == 1 ? w1 : w2;
    int e = blockIdx.x * blockDim.x + threadIdx.x;
    if (e < E) {
        int d = ei[E + e];
        atomicAdd(&g_dinv[br][d], w[e]);
        atomicAdd(&g_cnt[br][d], 1);
    }
}

// ---------------- scan phase A: per-1024-chunk exclusive scan + block total ----------------
// Also folds rsqrt(deg) (degcnt is complete by now).
__global__ void k_scanA() {
    int br = blockIdx.y;
    int base = blockIdx.x << 10;
    int t = threadIdx.x;
    int i = base + t;
    int lane = t & 31, wid = t >> 5;
    int v = (i < NN) ? g_cnt[br][i] : 0;
    if (i < NN) g_dinv[br][i] = rsqrtf(g_dinv[br][i]);
    // warp inclusive scan
    int x = v;
    #pragma unroll
    for (int o = 1; o < 32; o <<= 1) {
        int y = __shfl_up_sync(0xffffffffu, x, o);
        if (lane >= o) x += y;
    }
    __shared__ int wsum[32];
    if (lane == 31) wsum[wid] = x;
    __syncthreads();
    if (wid == 0) {
        int w = wsum[lane];
        #pragma unroll
        for (int o = 1; o < 32; o <<= 1) {
            int y = __shfl_up_sync(0xffffffffu, w, o);
            if (lane >= o) w += y;
        }
        wsum[lane] = w;
    }
    __syncthreads();
    int incl = x + (wid > 0 ? wsum[wid - 1] : 0);
    if (i < NN) g_offs[br][i] = incl - v;          // local exclusive prefix
    if (t == 1023) g_bsum[br][blockIdx.x] = incl;  // block total (i>=NN lanes contributed 0)
}

// ---------------- scan phase B: scan the 49 block totals per branch (1 block, 3 warps) ----------------
__global__ void k_scanB() {
    int br = threadIdx.x >> 5;
    int lane = threadIdx.x & 31;
    if (br >= 3) return;
    int a = (lane < NCHUNK) ? g_bsum[br][lane] : 0;
    int b = (lane + 32 < NCHUNK) ? g_bsum[br][lane + 32] : 0;
    int va = a, vb = b;
    #pragma unroll
    for (int o = 1; o < 32; o <<= 1) {
        int y = __shfl_up_sync(0xffffffffu, a, o);
        if (lane >= o) a += y;
        int z = __shfl_up_sync(0xffffffffu, b, o);
        if (lane >= o) b += z;
    }
    int totA = __shfl_sync(0xffffffffu, a, 31);
    int totB = __shfl_sync(0xffffffffu, b, 31);
    if (lane < NCHUNK) g_bsum[br][lane] = a - va;                 // exclusive
    if (lane + 32 < NCHUNK) g_bsum[br][lane + 32] = b - vb + totA;
    if (lane == 0) g_offs[br][NN] = totA + totB;                  // = E
}

// ---------------- scan phase C: add block offsets, init fill ----------------
__global__ void k_scanC() {
    int br = blockIdx.y;
    int i = (blockIdx.x << 10) + threadIdx.x;
    if (i < NN) {
        int o = g_offs[br][i] + g_bsum[br][blockIdx.x];
        g_offs[br][i] = o;
        g_fill[br][i] = o;
    }
}

// ---------------- bucket edges into CSR; norm computed here ----------------
__global__ void k_bucket(const int* __restrict__ s0, const int* __restrict__ s1, const int* __restrict__ s2,
                         const float* __restrict__ w0, const float* __restrict__ w1, const float* __restrict__ w2,
                         int E) {
    int br = blockIdx.y;
    const int* ei = br == 0 ? s0 : br == 1 ? s1 : s2;
    const float* w = br == 0 ? w0 : br == 1 ? w1 : w2;
    int e = blockIdx.x * blockDim.x + threadIdx.x;
    if (e >= E) return;
    int s = ei[e];
    int d = ei[E + e];
    float nv = g_dinv[br][s] * w[e] * g_dinv[br][d];
    int pos = atomicAdd(&g_fill[br][d], 1);
    g_csrc[br][pos] = s;
    g_cnorm[br][pos] = nv;
}

// ---------------- GEMM1 (tf32 mma, error-compensated): [NN,256]@[256,64] -> g_h ----------------
__global__ void k_gemm1(const float* __restrict__ X0, const float* __restrict__ X1, const float* __restrict__ X2,
                        const float* __restrict__ W0, const float* __restrict__ W1, const float* __restrict__ W2) {
    int br = blockIdx.y;
    const float* X = br == 0 ? X0 : br == 1 ? X1 : X2;
    const float* W = br == 0 ? W0 : br == 1 ? W1 : W2;

    __shared__ float xs_hi[128][20], xs_lo[128][20];
    __shared__ float ws_hi[16][72], ws_lo[16][72];

    int tid = threadIdx.x;
    int warp = tid >> 5, lane = tid & 31;
    int group = lane >> 2, tig = lane & 3;
    int m0 = blockIdx.x * 128;

    float c[8][4] = {};

    for (int k0 = 0; k0 < FIN; k0 += 16) {
        #pragma unroll
        for (int i = 0; i < 2; i++) {
            int idx = tid + i * 256;
            int r = idx >> 2;
            int cc = (idx & 3) * 4;
            float4 v = make_float4(0.f, 0.f, 0.f, 0.f);
            if (m0 + r < NN) v = *(const float4*)(X + (size_t)(m0 + r) * FIN + k0 + cc);
            float h0 = tf32r(v.x), h1 = tf32r(v.y), h2 = tf32r(v.z), h3 = tf32r(v.w);
            xs_hi[r][cc + 0] = h0; xs_hi[r][cc + 1] = h1; xs_hi[r][cc + 2] = h2; xs_hi[r][cc + 3] = h3;
            xs_lo[r][cc + 0] = tf32r(v.x - h0); xs_lo[r][cc + 1] = tf32r(v.y - h1);
            xs_lo[r][cc + 2] = tf32r(v.z - h2); xs_lo[r][cc + 3] = tf32r(v.w - h3);
        }
        {
            int kr = tid >> 4;
            int cc = (tid & 15) * 4;
            float4 v = *(const float4*)(W + (size_t)(k0 + kr) * FH + cc);
            float h0 = tf32r(v.x), h1 = tf32r(v.y), h2 = tf32r(v.z), h3 = tf32r(v.w);
            ws_hi[kr][cc + 0] = h0; ws_hi[kr][cc + 1] = h1; ws_hi[kr][cc + 2] = h2; ws_hi[kr][cc + 3] = h3;
            ws_lo[kr][cc + 0] = tf32r(v.x - h0); ws_lo[kr][cc + 1] = tf32r(v.y - h1);
            ws_lo[kr][cc + 2] = tf32r(v.z - h2); ws_lo[kr][cc + 3] = tf32r(v.w - h3);
        }
        __syncthreads();

        #pragma unroll
        for (int kk = 0; kk < 16; kk += 8) {
            int ar = warp * 16 + group;
            uint32_t a_hi[4], a_lo[4];
            a_hi[0] = __float_as_uint(xs_hi[ar][kk + tig]);
            a_hi[1] = __float_as_uint(xs_hi[ar + 8][kk + tig]);
            a_hi[2] = __float_as_uint(xs_hi[ar][kk + tig + 4]);
            a_hi[3] = __float_as_uint(xs_hi[ar + 8][kk + tig + 4]);
            a_lo[0] = __float_as_uint(xs_lo[ar][kk + tig]);
            a_lo[1] = __float_as_uint(xs_lo[ar + 8][kk + tig]);
            a_lo[2] = __float_as_uint(xs_lo[ar][kk + tig + 4]);
            a_lo[3] = __float_as_uint(xs_lo[ar + 8][kk + tig + 4]);
            #pragma unroll
            for (int nt = 0; nt < 8; nt++) {
                int n = nt * 8 + group;
                uint32_t bh0 = __float_as_uint(ws_hi[kk + tig][n]);
                uint32_t bh1 = __float_as_uint(ws_hi[kk + tig + 4][n]);
                uint32_t bl0 = __float_as_uint(ws_lo[kk + tig][n]);
                uint32_t bl1 = __float_as_uint(ws_lo[kk + tig + 4][n]);
                mma_tf32(c[nt], a_hi, bh0, bh1);
                mma_tf32(c[nt], a_lo, bh0, bh1);
                mma_tf32(c[nt], a_hi, bl0, bl1);
            }
        }
        __syncthreads();
    }

    float* H = &g_h[br][0];
    int r0 = m0 + warp * 16 + group;
    #pragma unroll
    for (int nt = 0; nt < 8; nt++) {
        int col = nt * 8 + tig * 2;
        if (r0 < NN)     *(float2*)(H + (size_t)r0 * FH + col)       = make_float2(c[nt][0], c[nt][1]);
        if (r0 + 8 < NN) *(float2*)(H + (size_t)(r0 + 8) * FH + col) = make_float2(c[nt][2], c[nt][3]);
    }
}

// ---------------- layer-1 aggregation: warp per node, gather-only, fused epilogue ----------------
__global__ void k_agg1(const float* __restrict__ b1, const float* __restrict__ b2,
                       const float* __restrict__ b3) {
    int br = blockIdx.y;
    int node = (blockIdx.x * blockDim.x + threadIdx.x) >> 5;
    int lane = threadIdx.x & 31;
    if (node >= NN) return;
    const float2* H2 = (const float2*)&g_h[br][0];
    const int*    cs = &g_csrc[br][0];
    const float*  cn = &g_cnorm[br][0];
    int j   = g_offs[br][node];
    int end = g_offs[br][node + 1];
    float2 acc0 = make_float2(0.f, 0.f), acc1 = make_float2(0.f, 0.f);
    for (; j + 2 <= end; j += 2) {
        int   s0 = cs[j],     s1 = cs[j + 1];
        float n0 = cn[j],     n1 = cn[j + 1];
        float2 h0 = H2[(size_t)s0 * 32 + lane];
        float2 h1 = H2[(size_t)s1 * 32 + lane];
        acc0.x += n0 * h0.x; acc0.y += n0 * h0.y;
        acc1.x += n1 * h1.x; acc1.y += n1 * h1.y;
    }
    if (j < end) {
        int s0 = cs[j]; float n0 = cn[j];
        float2 h0 = H2[(size_t)s0 * 32 + lane];
        acc0.x += n0 * h0.x; acc0.y += n0 * h0.y;
    }
    float di = g_dinv[br][node]; di *= di;
    float2 hn = H2[(size_t)node * 32 + lane];
    const float* b = br == 0 ? b1 : br == 1 ? b2 : b3;
    float2 bb = ((const float2*)b)[lane];
    float2 ev;
    ev.x = fmaxf(acc0.x + acc1.x + di * hn.x + bb.x, 0.f);
    ev.y = fmaxf(acc0.y + acc1.y + di * hn.y + bb.y, 0.f);
    ((float2*)&g_e[br][0])[(size_t)node * 32 + lane] = ev;
}

// ---------------- attention: warp per node (e already relu'd) ----------------
__global__ void k_attn(const float* __restrict__ fcw, const float* __restrict__ fcb,
                       float* __restrict__ out_coef) {
    int node = (blockIdx.x * blockDim.x + threadIdx.x) >> 5;
    int lane = threadIdx.x & 31;
    if (node >= NN) return;
    float2 e1 = ((const float2*)&g_e[0][0])[(size_t)node * 32 + lane];
    float2 e2 = ((const float2*)&g_e[1][0])[(size_t)node * 32 + lane];
    float2 e3 = ((const float2*)&g_e[2][0])[(size_t)node * 32 + lane];
    float2 w2 = ((const float2*)fcw)[lane];
    float d1 = e1.x * w2.x + e1.y * w2.y;
    float d2 = e2.x * w2.x + e2.y * w2.y;
    float d3 = e3.x * w2.x + e3.y * w2.y;
    #pragma unroll
    for (int o = 16; o > 0; o >>= 1) {
        d1 += __shfl_xor_sync(0xffffffffu, d1, o);
        d2 += __shfl_xor_sync(0xffffffffu, d2, o);
        d3 += __shfl_xor_sync(0xffffffffu, d3, o);
    }
    float fb = fcb[0];
    float v1 = d1 + fb, v2 = d2 + fb, v3 = d3 + fb;
    v1 = v1 > 0.f ? v1 : v1 * NEG_SLOPE;
    v2 = v2 > 0.f ? v2 : v2 * NEG_SLOPE;
    v3 = v3 > 0.f ? v3 : v3 * NEG_SLOPE;
    float x1 = expf(v1), x2 = expf(v2), x3 = expf(v3);
    float inv = 1.0f / (x1 + x2 + x3);
    float c1 = x1 * inv, c2 = x2 * inv, c3 = x3 * inv;
    float2 cmb;
    cmb.x = c1 * e1.x + c2 * e2.x + c3 * e3.x;
    cmb.y = c1 * e1.y + c2 * e2.y + c3 * e3.y;
    ((float2*)g_comb)[(size_t)node * 32 + lane] = cmb;
    if (lane == 0) {
        out_coef[node]          = c1;
        out_coef[NN + node]     = c2;
        out_coef[2 * NN + node] = c3;
    }
}

// ---------------- GEMM2: [NN,64] @ [64,32] -> g_g[br] ----------------
__global__ void k_gemm2(const float* __restrict__ Wa, const float* __restrict__ Wb,
                        const float* __restrict__ Wc) {
    int br = blockIdx.y;
    const float* W2 = br == 0 ? Wa : br == 1 ? Wb : Wc;
    __shared__ float ws[64][32];
    __shared__ float cs[32][65];
    int tid = threadIdx.x;
    int r0 = blockIdx.x * 32;
    for (int i = tid; i < 512; i += 256)
        ((float4*)ws)[i] = ((const float4*)W2)[i];
    for (int i = tid; i < 512; i += 256) {
        int row = i >> 4, c = (i & 15) * 4;
        int gr = r0 + row;
        float4 v = make_float4(0.f, 0.f, 0.f, 0.f);
        if (gr < NN) v = ((const float4*)g_comb)[(size_t)gr * 16 + (c >> 2)];
        cs[row][c] = v.x; cs[row][c + 1] = v.y; cs[row][c + 2] = v.z; cs[row][c + 3] = v.w;
    }
    __syncthreads();
    int row = tid >> 3, cg = (tid & 7) * 4;
    float4 acc = make_float4(0.f, 0.f, 0.f, 0.f);
    #pragma unroll
    for (int k = 0; k < 64; k++) {
        float a = cs[row][k];
        float4 b = *(const float4*)&ws[k][cg];
        acc.x += a * b.x; acc.y += a * b.y; acc.z += a * b.z; acc.w += a * b.w;
    }
    int gr = r0 + row;
    if (gr < NN)
        ((float4*)&g_g[br][0])[(size_t)gr * 8 + (cg >> 2)] = acc;
}

// ---------------- layer-2 aggregation: warp per node, all 3 branches, write d_out ----------------
__global__ void k_agg2(const float* __restrict__ b11, const float* __restrict__ b22,
                       const float* __restrict__ b33, float* __restrict__ out) {
    int node = (blockIdx.x * blockDim.x + threadIdx.x) >> 5;
    int lane = threadIdx.x & 31;
    if (node >= NN) return;
    float acc = 0.f;
    #pragma unroll
    for (int br = 0; br < 3; br++) {
        const float* G  = &g_g[br][0];
        const int*   cs = &g_csrc[br][0];
        const float* cn = &g_cnorm[br][0];
        int j   = g_offs[br][node];
        int end = g_offs[br][node + 1];
        float a0 = 0.f, a1 = 0.f;
        for (; j + 2 <= end; j += 2) {
            int   s0 = cs[j],  s1 = cs[j + 1];
            float n0 = cn[j],  n1 = cn[j + 1];
            a0 += n0 * G[(size_t)s0 * FOUT + lane];
            a1 += n1 * G[(size_t)s1 * FOUT + lane];
        }
        if (j < end) a0 += cn[j] * G[(size_t)cs[j] * FOUT + lane];
        float di = g_dinv[br][node]; di *= di;
        acc += a0 + a1 + di * G[(size_t)node * FOUT + lane];
    }
    acc += b11[lane] + b22[lane] + b33[lane];
    out[(size_t)node * FOUT + lane] = acc;
}

// ---------------- launch ----------------
extern "C" void kernel_launch(void* const* d_in, const int* in_sizes, int n_in,
                              void* d_out, int out_size) {
    const float* x[3]  = {(const float*)d_in[0], (const float*)d_in[1], (const float*)d_in[2]};
    const int*   ei[3] = {(const int*)d_in[3], (const int*)d_in[4], (const int*)d_in[5]};
    const float* ew[3] = {(const float*)d_in[6], (const float*)d_in[7], (const float*)d_in[8]};
    const float* W1[3] = {(const float*)d_in[9], (const float*)d_in[10], (const float*)d_in[11]};
    const float* b1[3] = {(const float*)d_in[12], (const float*)d_in[13], (const float*)d_in[14]};
    const float* fcw   = (const float*)d_in[15];
    const float* fcb   = (const float*)d_in[16];
    const float* W2[3] = {(const float*)d_in[17], (const float*)d_in[18], (const float*)d_in[19]};
    const float* b2[3] = {(const float*)d_in[20], (const float*)d_in[21], (const float*)d_in[22]};
    float* out = (float*)d_out;

    int E = in_sizes[3] / 2;

    k_init<<<256, 256>>>();

    {   dim3 g((E + 255) / 256, 3);
        k_degcnt<<<g, 256>>>(ei[0], ei[1], ei[2], ew[0], ew[1], ew[2], E); }

    {   dim3 g(NCHUNK, 3);
        k_scanA<<<g, 1024>>>(); }

    k_scanB<<<1, 96>>>();

    {   dim3 g(NCHUNK, 3);
        k_scanC<<<g, 1024>>>(); }

    {   dim3 g((E + 255) / 256, 3);
        k_bucket<<<g, 256>>>(ei[0], ei[1], ei[2], ew[0], ew[1], ew[2], E); }

    {   dim3 g((NN + 127) / 128, 3);
        k_gemm1<<<g, 256>>>(x[0], x[1], x[2], W1[0], W1[1], W1[2]); }

    {   dim3 g((NN * 32 + 255) / 256, 3);
        k_agg1<<<g, 256>>>(b1[0], b1[1], b1[2]); }

    k_attn<<<(NN * 32 + 255) / 256, 256>>>(fcw, fcb, out + NN * FOUT);

    {   dim3 g((NN + 31) / 32, 3);
        k_gemm2<<<g, 256>>>(W2[0], W2[1], W2[2]); }

    k_agg2<<<(NN * 32 + 255) / 256, 256>>>(b2[0], b2[1], b2[2], out);
}